// round 6
// baseline (speedup 1.0000x reference)
#include <cuda_runtime.h>

// Single CTA, 512 threads. Twiddle tables (with mean-removal and MTI folded in)
// live in __constant__ memory -> LDC broadcasts, no smem staging. Packed f32x2 FMAs.

typedef unsigned long long u64;

constexpr double PI_D = 3.14159265358979323846264338327950288;

constexpr double d_sin(double x) {
    double t = x, s = x, x2 = x * x;
    for (int n = 1; n <= 11; ++n) { t *= -x2 / double((2*n)*(2*n+1)); s += t; }
    return s;
}
constexpr double d_cos(double x) {
    double t = 1.0, s = 1.0, x2 = x * x;
    for (int n = 1; n <= 11; ++n) { t *= -x2 / double((2*n-1)*(2*n)); s += t; }
    return s;
}
constexpr double d_sqrt(double x) {
    if (x <= 0.0) return 0.0;
    double r = x > 1.0 ? x : 1.0;
    for (int i = 0; i < 40; ++i) r = 0.5 * (r + x / r);
    return r;
}
constexpr double d_i0(double x) {
    double t = 1.0, s = 1.0, q = x * 0.5;
    for (int m = 1; m <= 70; ++m) { double u = q / m; t *= u * u; s += t; }
    return s;
}
constexpr double red(double a) {
    while (a < -PI_D) a += 2.0 * PI_D;
    while (a >  PI_D) a -= 2.0 * PI_D;
    return a;
}

struct alignas(16) Tab {
    // t1[s][k][2]: rw[s]*exp(-2pi*i*k*s/64) - RK[k]/64   (hann + mean-removal fold)
    float t1[64][32][2];
    // t2[c][d][4]: (a,b,b,a), a+ib = dw[c]*exp(-2pi*i*d*c/32) - WD[d]/32 (kaiser + MTI fold)
    float t2[32][32][4];
};

constexpr Tab make_tab() {
    Tab T{};
    double rw[64] = {}; double rsum = 0.0;
    for (int n = 0; n < 64; ++n) { rw[n] = 0.5 - 0.5 * d_cos(red(2.0*PI_D*n/63.0)); rsum += rw[n]; }
    for (int n = 0; n < 64; ++n) rw[n] /= rsum;
    double dw[32] = {}; double dsum = 0.0; double i025 = d_i0(25.0);
    for (int n = 0; n < 32; ++n) {
        double al = 15.5, tt = (n - al) / al, arg = 1.0 - tt*tt;
        dw[n] = d_i0(25.0 * d_sqrt(arg < 0.0 ? 0.0 : arg)) / i025; dsum += dw[n];
    }
    for (int n = 0; n < 32; ++n) dw[n] /= dsum;
    for (int k = 0; k < 32; ++k) {
        double rkr = 0.0, rki = 0.0;
        for (int s = 0; s < 64; ++s) {
            double ang = red(-2.0*PI_D*double((k*s)&63)/64.0);
            rkr += rw[s]*d_cos(ang); rki += rw[s]*d_sin(ang);
        }
        for (int s = 0; s < 64; ++s) {
            double ang = red(-2.0*PI_D*double((k*s)&63)/64.0);
            T.t1[s][k][0] = (float)(rw[s]*d_cos(ang) - rkr/64.0);
            T.t1[s][k][1] = (float)(rw[s]*d_sin(ang) - rki/64.0);
        }
    }
    for (int d = 0; d < 32; ++d) {
        double wdr = 0.0, wdi = 0.0;
        for (int c = 0; c < 32; ++c) {
            double ang = red(-2.0*PI_D*double((d*c)&31)/32.0);
            wdr += dw[c]*d_cos(ang); wdi += dw[c]*d_sin(ang);
        }
        for (int c = 0; c < 32; ++c) {
            double ang = red(-2.0*PI_D*double((d*c)&31)/32.0);
            double a = dw[c]*d_cos(ang) - wdr/32.0;
            double b = dw[c]*d_sin(ang) - wdi/32.0;
            T.t2[c][d][0] = (float)a; T.t2[c][d][1] = (float)b;
            T.t2[c][d][2] = (float)b; T.t2[c][d][3] = (float)a;
        }
    }
    return T;
}

__constant__ Tab c_tab = make_tab();

__device__ __forceinline__ u64 pk(float lo, float hi) {
    u64 r; asm("mov.b64 %0, {%1,%2};" : "=l"(r) : "f"(lo), "f"(hi)); return r;
}
__device__ __forceinline__ void upk(u64 v, float& lo, float& hi) {
    asm("mov.b64 {%0,%1}, %2;" : "=f"(lo), "=f"(hi) : "l"(v));
}
__device__ __forceinline__ u64 ffma2(u64 a, u64 b, u64 c) {
    u64 d; asm("fma.rn.f32x2 %0, %1, %2, %3;" : "=l"(d) : "l"(a), "l"(b), "l"(c)); return d;
}

// smem: x[32][65] (img[32][33] overlays it in stage 2), Xr[32][33], Xi[32][33]
__global__ __launch_bounds__(512) void rdm_kernel(const float* __restrict__ frame,
                                                  float* __restrict__ out)
{
    __shared__ float s_x[32 * 65];
    __shared__ float s_Xr[32 * 33];
    __shared__ float s_Xi[32 * 33];

    const int tid  = threadIdx.x;
    const int lane = tid & 31;
    const int warp = tid >> 5;

    // ---- stage frame[0] into padded smem (only global->smem traffic) ----
    #pragma unroll
    for (int i = 0; i < 4; ++i) {
        int idx = tid + i * 512;               // 0..2047
        s_x[(idx >> 6) * 65 + (idx & 63)] = frame[idx];
    }
    __syncthreads();

    // ---- stage 1: range DFT. warp -> k = 2*warp, 2*warp+1; lane = c ----
    {
        const int c = lane, k2 = warp << 1;
        const float* xrow = s_x + c * 65;      // LDS [R + imm] after unroll
        u64 a0 = 0, a1 = 0;
        #pragma unroll
        for (int s = 0; s < 64; ++s) {
            float v = xrow[s];
            u64 vv = pk(v, v);
            // warp-uniform constant load: 2 packed complex twiddles (16B)
            ulonglong2 t = *(const ulonglong2*)&c_tab.t1[s][k2][0];
            a0 = ffma2(vv, t.x, a0);
            a1 = ffma2(vv, t.y, a1);
        }
        float r0, i0v, r1, i1v;
        upk(a0, r0, i0v); upk(a1, r1, i1v);
        s_Xr[c * 33 + k2 + 0] = r0;  s_Xi[c * 33 + k2 + 0] = i0v;
        s_Xr[c * 33 + k2 + 1] = r1;  s_Xi[c * 33 + k2 + 1] = i1v;
    }
    __syncthreads();

    // ---- stage 2: doppler DFT (+folded MTI) + epilogue. warp -> d = 2w,2w+1; lane = k ----
    {
        const int k = lane, d2 = warp << 1;
        u64 z0 = 0, z1 = 0;
        #pragma unroll
        for (int c = 0; c < 32; ++c) {
            float xr = s_Xr[c * 33 + k];       // LDS [R + imm], conflict-free
            float xi = s_Xi[c * 33 + k];
            u64 v1 = pk(xr, xr);
            u64 v2 = pk(-xi, xi);
            ulonglong2 tA = *(const ulonglong2*)&c_tab.t2[c][d2 + 0][0]; // (a,b),(b,a)
            ulonglong2 tB = *(const ulonglong2*)&c_tab.t2[c][d2 + 1][0];
            z0 = ffma2(v1, tA.x, ffma2(v2, tA.y, z0));
            z1 = ffma2(v1, tB.x, ffma2(v2, tB.y, z1));
        }
        float* img = s_x;                      // frame area dead now
        u64 zz[2] = {z0, z1};
        #pragma unroll
        for (int dd = 0; dd < 2; ++dd) {
            float zr, zi; upk(zz[dd], zr, zi);
            float mag = sqrtf(zr * zr + zi * zi) * 1000.0f;
            float v = fminf(fmaxf(mag, 0.0f), 1.0f) * 255.0f;
            img[(31 - k) * 33 + ((d2 + dd + 16) & 31)] = truncf(v);
        }
    }
    __syncthreads();

    // ---- coalesced output: 256 threads x float4 ----
    if (tid < 256) {
        const float* img = s_x;
        int row = tid >> 3, col = (tid & 7) << 2;
        float4 o;
        o.x = img[row * 33 + col + 0];
        o.y = img[row * 33 + col + 1];
        o.z = img[row * 33 + col + 2];
        o.w = img[row * 33 + col + 3];
        ((float4*)out)[tid] = o;
    }
}

extern "C" void kernel_launch(void* const* d_in, const int* in_sizes, int n_in,
                              void* d_out, int out_size)
{
    (void)in_sizes; (void)n_in; (void)out_size;
    rdm_kernel<<<1, 512>>>((const float*)d_in[0], (float*)d_out);
}

// round 7
// speedup vs baseline: 1.9412x; 1.9412x over previous
#include <cuda_runtime.h>

// Single CTA, 1024 threads. Twiddle tables (mean-removal + MTI folded) staged
// into smem as planar re/im. All smem traffic is LDS.128; packed f32x2 FMAs
// accumulate even/odd partial sums (no packing MOVs).

typedef unsigned long long u64;

constexpr double PI_D = 3.14159265358979323846264338327950288;

constexpr double d_sin(double x) {
    double t = x, s = x, x2 = x * x;
    for (int n = 1; n <= 11; ++n) { t *= -x2 / double((2*n)*(2*n+1)); s += t; }
    return s;
}
constexpr double d_cos(double x) {
    double t = 1.0, s = 1.0, x2 = x * x;
    for (int n = 1; n <= 11; ++n) { t *= -x2 / double((2*n-1)*(2*n)); s += t; }
    return s;
}
constexpr double d_sqrt(double x) {
    if (x <= 0.0) return 0.0;
    double r = x > 1.0 ? x : 1.0;
    for (int i = 0; i < 40; ++i) r = 0.5 * (r + x / r);
    return r;
}
constexpr double d_i0(double x) {
    double t = 1.0, s = 1.0, q = x * 0.5;
    for (int m = 1; m <= 70; ++m) { double u = q / m; t *= u * u; s += t; }
    return s;
}
constexpr double red(double a) {
    while (a < -PI_D) a += 2.0 * PI_D;
    while (a >  PI_D) a -= 2.0 * PI_D;
    return a;
}

struct alignas(16) Tab {
    float t1r[32][64];   // [k][s]: Re(rw[s]*e^{-2pi i ks/64}) - RKr[k]/64
    float t1i[32][64];
    float t2r[32][32];   // [d][c]: Re(dw[c]*e^{-2pi i dc/32}) - WDr[d]/32
    float t2i[32][32];
};
#define TAB_F4 1536      // 24KB / 16

constexpr Tab make_tab() {
    Tab T{};
    double rw[64] = {}; double rsum = 0.0;
    for (int n = 0; n < 64; ++n) { rw[n] = 0.5 - 0.5 * d_cos(red(2.0*PI_D*n/63.0)); rsum += rw[n]; }
    for (int n = 0; n < 64; ++n) rw[n] /= rsum;
    double dw[32] = {}; double dsum = 0.0; double i025 = d_i0(25.0);
    for (int n = 0; n < 32; ++n) {
        double al = 15.5, tt = (n - al) / al, arg = 1.0 - tt*tt;
        dw[n] = d_i0(25.0 * d_sqrt(arg < 0.0 ? 0.0 : arg)) / i025; dsum += dw[n];
    }
    for (int n = 0; n < 32; ++n) dw[n] /= dsum;
    for (int k = 0; k < 32; ++k) {
        double rkr = 0.0, rki = 0.0;
        for (int s = 0; s < 64; ++s) {
            double ang = red(-2.0*PI_D*double((k*s)&63)/64.0);
            rkr += rw[s]*d_cos(ang); rki += rw[s]*d_sin(ang);
        }
        for (int s = 0; s < 64; ++s) {
            double ang = red(-2.0*PI_D*double((k*s)&63)/64.0);
            T.t1r[k][s] = (float)(rw[s]*d_cos(ang) - rkr/64.0);
            T.t1i[k][s] = (float)(rw[s]*d_sin(ang) - rki/64.0);
        }
    }
    for (int d = 0; d < 32; ++d) {
        double wdr = 0.0, wdi = 0.0;
        for (int c = 0; c < 32; ++c) {
            double ang = red(-2.0*PI_D*double((d*c)&31)/32.0);
            wdr += dw[c]*d_cos(ang); wdi += dw[c]*d_sin(ang);
        }
        for (int c = 0; c < 32; ++c) {
            double ang = red(-2.0*PI_D*double((d*c)&31)/32.0);
            T.t2r[d][c] = (float)(dw[c]*d_cos(ang) - wdr/32.0);
            T.t2i[d][c] = (float)(dw[c]*d_sin(ang) - wdi/32.0);
        }
    }
    return T;
}

__device__ const Tab g_tab = make_tab();

__device__ __forceinline__ void upk(u64 v, float& lo, float& hi) {
    asm("mov.b64 {%0,%1}, %2;" : "=f"(lo), "=f"(hi) : "l"(v));
}
__device__ __forceinline__ u64 ffma2(u64 a, u64 b, u64 c) {
    u64 d; asm("fma.rn.f32x2 %0, %1, %2, %3;" : "=l"(d) : "l"(a), "l"(b), "l"(c)); return d;
}
__device__ __forceinline__ float psum(u64 v) { float lo, hi; upk(v, lo, hi); return lo + hi; }

// x pitch 68 floats (16B-stride 17, odd -> LDS.128 conflict-free)
// X pitch 36 floats (16B-stride 9, odd)
#define XP 68
#define KP 36

__global__ __launch_bounds__(1024) void rdm_kernel(const float* __restrict__ frame,
                                                   float* __restrict__ out)
{
    __shared__ __align__(16) float s_tab[TAB_F4 * 4];   // 24KB planar tables
    __shared__ __align__(16) float s_x[32 * XP];        // [c][s] (img overlays later)
    __shared__ __align__(16) float s_Xr[32 * KP];       // [k][c]
    __shared__ __align__(16) float s_Xi[32 * KP];

    const int tid  = threadIdx.x;
    const int lane = tid & 31;
    const int warp = tid >> 5;

    // ---- stage tables (1536 float4) and frame (512 float4) ----
    {
        const float4* src = (const float4*)&g_tab;
        float4* dst = (float4*)s_tab;
        dst[tid] = src[tid];
        if (tid < 512) {
            dst[1024 + tid] = src[1024 + tid];
            float4 fv = ((const float4*)frame)[tid];      // frame[0]: 2048 floats
            int c = tid >> 4, s4 = (tid & 15) << 2;
            *(float4*)(s_x + c * XP + s4) = fv;
        }
    }
    __syncthreads();

    const float* T1r = s_tab;
    const float* T1i = s_tab + 2048;
    const float* T2r = s_tab + 4096;
    const float* T2i = s_tab + 5120;

    // ---- stage 1: range DFT. warp=k, lane=c. acc = packed even/odd-s partials ----
    {
        const int k = warp, c = lane;
        const float* xrow = s_x + c * XP;
        const float* tr = T1r + k * 64;
        const float* ti = T1i + k * 64;
        u64 ar = 0, ai = 0;
        #pragma unroll
        for (int s = 0; s < 64; s += 4) {
            ulonglong2 xv = *(const ulonglong2*)(xrow + s);   // (x0,x1),(x2,x3)
            ulonglong2 tv = *(const ulonglong2*)(tr + s);     // broadcast
            ulonglong2 uv = *(const ulonglong2*)(ti + s);     // broadcast
            ar = ffma2(xv.x, tv.x, ar);
            ar = ffma2(xv.y, tv.y, ar);
            ai = ffma2(xv.x, uv.x, ai);
            ai = ffma2(xv.y, uv.y, ai);
        }
        s_Xr[k * KP + c] = psum(ar);
        s_Xi[k * KP + c] = psum(ai);
    }
    __syncthreads();

    // ---- stage 2: doppler DFT (+folded MTI) + epilogue. warp=d, lane=k ----
    {
        const int d = warp, k = lane;
        const float* xrp = s_Xr + k * KP;
        const float* xip = s_Xi + k * KP;
        const float* tr = T2r + d * 32;
        const float* ti = T2i + d * 32;
        u64 A = 0, B = 0, C = 0, D = 0;   // Σxr*a, Σxi*b, Σxr*b, Σxi*a
        #pragma unroll
        for (int c = 0; c < 32; c += 4) {
            ulonglong2 xr2 = *(const ulonglong2*)(xrp + c);
            ulonglong2 xi2 = *(const ulonglong2*)(xip + c);
            ulonglong2 a2  = *(const ulonglong2*)(tr + c);    // broadcast
            ulonglong2 b2  = *(const ulonglong2*)(ti + c);    // broadcast
            A = ffma2(xr2.x, a2.x, A); A = ffma2(xr2.y, a2.y, A);
            B = ffma2(xi2.x, b2.x, B); B = ffma2(xi2.y, b2.y, B);
            C = ffma2(xr2.x, b2.x, C); C = ffma2(xr2.y, b2.y, C);
            D = ffma2(xi2.x, a2.x, D); D = ffma2(xi2.y, a2.y, D);
        }
        float zr = psum(A) - psum(B);
        float zi = psum(C) + psum(D);
        float mag = sqrtf(zr * zr + zi * zi) * 1000.0f;
        float v = fminf(fmaxf(mag, 0.0f), 1.0f) * 255.0f;
        float* img = s_x;   // frame area dead now
        img[(31 - k) * 33 + ((d + 16) & 31)] = truncf(v);
    }
    __syncthreads();

    // ---- coalesced output: 256 threads x float4 ----
    if (tid < 256) {
        const float* img = s_x;
        int row = tid >> 3, col = (tid & 7) << 2;
        float4 o;
        o.x = img[row * 33 + col + 0];
        o.y = img[row * 33 + col + 1];
        o.z = img[row * 33 + col + 2];
        o.w = img[row * 33 + col + 3];
        ((float4*)out)[tid] = o;
    }
}

extern "C" void kernel_launch(void* const* d_in, const int* in_sizes, int n_in,
                              void* d_out, int out_size)
{
    (void)in_sizes; (void)n_in; (void)out_size;
    rdm_kernel<<<1, 1024>>>((const float*)d_in[0], (float*)d_out);
}